// round 1
// baseline (speedup 1.0000x reference)
#include <cuda_runtime.h>

#define D_MODEL 1024
#define NH      16
#define DK      64
#define BB      2
#define TQN     2048
#define TPAST   2048
#define TKV     4096

// Scratch (device globals: no allocation allowed in kernel_launch)
__device__ float g_Q[(size_t)BB * NH * TQN * DK];       // [b,h,t,dk]  16 MB
__device__ float g_att[(size_t)BB * TQN * D_MODEL];     // [b,t,d]     16 MB

// ---------------------------------------------------------------------------
// GEMM core: computes a 128x128 tile of  C = A[M,1024] @ W[1024,1024]^T
// A row-major [M,1024], W row-major [1024,1024] (both K-contiguous -> NT gemm)
// 256 threads, 8x8 register micro-tile per thread, K-tile = 16.
// ---------------------------------------------------------------------------
__device__ __forceinline__ void gemm128(const float* __restrict__ A,
                                        const float* __restrict__ W,
                                        float acc[8][8])
{
    __shared__ float As[16][132];   // [k][m], padded stride 132 (bank-friendly)
    __shared__ float Bs[16][132];   // [k][n]

    const int tid = threadIdx.x;
    const int tx = tid & 15, ty = tid >> 4;
    const int m0 = blockIdx.y << 7, n0 = blockIdx.x << 7;

#pragma unroll
    for (int i = 0; i < 8; i++)
#pragma unroll
        for (int j = 0; j < 8; j++) acc[i][j] = 0.f;

    for (int k0 = 0; k0 < 1024; k0 += 16) {
#pragma unroll
        for (int i = 0; i < 2; i++) {
            int idx = tid + (i << 8);
            int row = idx >> 2, c4 = (idx & 3) << 2;
            float4 va = *(const float4*)(A + (size_t)(m0 + row) * 1024 + k0 + c4);
            As[c4 + 0][row] = va.x; As[c4 + 1][row] = va.y;
            As[c4 + 2][row] = va.z; As[c4 + 3][row] = va.w;
            float4 vb = *(const float4*)(W + (size_t)(n0 + row) * 1024 + k0 + c4);
            Bs[c4 + 0][row] = vb.x; Bs[c4 + 1][row] = vb.y;
            Bs[c4 + 2][row] = vb.z; Bs[c4 + 3][row] = vb.w;
        }
        __syncthreads();
#pragma unroll
        for (int kk = 0; kk < 16; kk++) {
            float a[8], b[8];
            *(float4*)(a)     = *(const float4*)&As[kk][ty * 8];
            *(float4*)(a + 4) = *(const float4*)&As[kk][ty * 8 + 4];
            *(float4*)(b)     = *(const float4*)&Bs[kk][tx * 8];
            *(float4*)(b + 4) = *(const float4*)&Bs[kk][tx * 8 + 4];
#pragma unroll
            for (int i = 0; i < 8; i++)
#pragma unroll
                for (int j = 0; j < 8; j++)
                    acc[i][j] = fmaf(a[i], b[j], acc[i][j]);
        }
        __syncthreads();
    }
}

// ---------------------------------------------------------------------------
// QKV projection: z=0 -> Q (to g_Q scratch, [b,h,t,dk]),
//                 z=1 -> K, z=2 -> V (scattered into KV-cache region of d_out
//                 at time offset TPAST)
// ---------------------------------------------------------------------------
__global__ __launch_bounds__(256) void qkv_kernel(
    const float* __restrict__ q_in, const float* __restrict__ k_in,
    const float* __restrict__ v_in,
    const float* __restrict__ Wq, const float* __restrict__ bq,
    const float* __restrict__ Wk, const float* __restrict__ bk,
    const float* __restrict__ Wv, const float* __restrict__ bv,
    float* __restrict__ k_out, float* __restrict__ v_out)
{
    const int z = blockIdx.z;
    const float* A    = (z == 0) ? q_in : (z == 1) ? k_in : v_in;
    const float* W    = (z == 0) ? Wq   : (z == 1) ? Wk   : Wv;
    const float* bias = (z == 0) ? bq   : (z == 1) ? bk   : bv;

    float acc[8][8];
    gemm128(A, W, acc);

    const int tx = threadIdx.x & 15, ty = threadIdx.x >> 4;
    const int m0 = blockIdx.y << 7, n0 = blockIdx.x << 7;
#pragma unroll
    for (int i = 0; i < 8; i++) {
        int m  = m0 + ty * 8 + i;
        int bb = m >> 11, tt = m & 2047;       // b = m / TQN, t = m % TQN
#pragma unroll
        for (int j = 0; j < 8; j++) {
            int n = n0 + tx * 8 + j;
            float val = acc[i][j] + bias[n];
            int h = n >> 6, dk = n & 63;
            if (z == 0) {
                g_Q[(((size_t)(bb * NH + h)) * TQN + tt) * DK + dk] = val;
            } else {
                float* dst = (z == 1) ? k_out : v_out;
                dst[(((size_t)(bb * NH + h)) * TKV + TPAST + tt) * DK + dk] = val;
            }
        }
    }
}

// ---------------------------------------------------------------------------
// Copy past_K / past_V into the first TPAST slots of the KV cache outputs.
// ---------------------------------------------------------------------------
__global__ __launch_bounds__(256) void copy_past_kernel(
    const float4* __restrict__ pk, const float4* __restrict__ pv,
    float4* __restrict__ ko, float4* __restrict__ vo)
{
    const int PER_BH_SRC = TPAST * DK / 4;   // 32768 float4 per (b,h)
    const int PER_BH_DST = TKV   * DK / 4;   // 65536
    const int TOT = BB * NH * PER_BH_SRC;    // 1048576 per tensor
    int idx = blockIdx.x * blockDim.x + threadIdx.x;   // grid covers 2*TOT
    int which = idx >= TOT;
    int r = idx - (which ? TOT : 0);
    int bhi = r / PER_BH_SRC;
    int off = r - bhi * PER_BH_SRC;
    const float4* src = which ? pv : pk;
    float4*       dst = which ? vo : ko;
    dst[(size_t)bhi * PER_BH_DST + off] = src[r];
}

// ---------------------------------------------------------------------------
// Flash attention. One block = one (b,h) and a 64-query tile. 128 threads.
// Online softmax over KV tiles of 64. Causal: exactly one partial tile.
// SMEM: three 64x64 fp32 tiles (48 KB exactly), XOR-swizzled.
// ---------------------------------------------------------------------------
#define SW(r, c) ((((r) << 6) | ((c) ^ (r))))

__global__ __launch_bounds__(128) void flash_kernel(const float* __restrict__ kc,
                                                    const float* __restrict__ vc)
{
    __shared__ float Qs[64 * 64];
    __shared__ float KtP[64 * 64];   // K^T tile, then reused for P tile
    __shared__ float Vs[64 * 64];

    const int tid = threadIdx.x;
    const int tx = tid & 7;          // 8 column-groups of 8
    const int ty = tid >> 3;         // 16 row-groups of 4
    const int q0 = blockIdx.x << 6;
    const int bh = blockIdx.y;

    const float* Qg = g_Q + (size_t)bh * TQN * DK + (size_t)q0 * DK;
    const float* Kg = kc + (size_t)bh * TKV * DK;
    const float* Vg = vc + (size_t)bh * TKV * DK;

    // load Q tile (pre-scaled by 1/sqrt(dk) = 1/8)
    for (int idx = tid; idx < 64 * 64; idx += 128) {
        int r = idx >> 6, d = idx & 63;
        Qs[SW(r, d)] = Qg[(size_t)r * DK + d] * 0.125f;
    }

    float m_i[4], l_i[4], O[4][8];
#pragma unroll
    for (int i = 0; i < 4; i++) {
        m_i[i] = -1e30f; l_i[i] = 0.f;
#pragma unroll
        for (int c = 0; c < 8; c++) O[i][c] = 0.f;
    }

    const int n_tiles = ((TPAST + q0) >> 6) + 1;   // last tile is the partial one
    for (int t = 0; t < n_tiles; t++) {
        const int j0 = t << 6;
        __syncthreads();   // previous iteration done with KtP/Vs (also covers Qs load)

        // load K tile transposed: KtP[d][j] = K[j0+j][d]
        {
            int d = tid & 63, jj = tid >> 6;
#pragma unroll 4
            for (int j = jj; j < 64; j += 2)
                KtP[SW(d, j)] = Kg[(size_t)(j0 + j) * DK + d];
        }
        // load V tile row-major
        for (int idx = tid; idx < 64 * 64; idx += 128) {
            int r = idx >> 6, d = idx & 63;
            Vs[SW(r, d)] = Vg[(size_t)(j0 + r) * DK + d];
        }
        __syncthreads();

        // S = Q @ K^T   (thread owns rows ty*4..+3, cols tx*8..+7)
        float s[4][8];
#pragma unroll
        for (int i = 0; i < 4; i++)
#pragma unroll
            for (int c = 0; c < 8; c++) s[i][c] = 0.f;

#pragma unroll 4
        for (int kk = 0; kk < 64; kk++) {
            float qf[4], kf[8];
#pragma unroll
            for (int i = 0; i < 4; i++) qf[i] = Qs[SW(ty * 4 + i, kk)];
#pragma unroll
            for (int c = 0; c < 8; c++) kf[c] = KtP[SW(kk, tx * 8 + c)];
#pragma unroll
            for (int i = 0; i < 4; i++)
#pragma unroll
                for (int c = 0; c < 8; c++)
                    s[i][c] = fmaf(qf[i], kf[c], s[i][c]);
        }

        // causal mask: query (q0+r) attends kv j <= TPAST + q0 + r
        if (t == n_tiles - 1) {
#pragma unroll
            for (int i = 0; i < 4; i++)
#pragma unroll
                for (int c = 0; c < 8; c++)
                    if (j0 + tx * 8 + c > TPAST + q0 + ty * 4 + i)
                        s[i][c] = -1e30f;
        }

        // online softmax (row stats shared across the 8 lanes with same ty)
#pragma unroll
        for (int i = 0; i < 4; i++) {
            float mx = s[i][0];
#pragma unroll
            for (int c = 1; c < 8; c++) mx = fmaxf(mx, s[i][c]);
            mx = fmaxf(mx, __shfl_xor_sync(0xffffffffu, mx, 1));
            mx = fmaxf(mx, __shfl_xor_sync(0xffffffffu, mx, 2));
            mx = fmaxf(mx, __shfl_xor_sync(0xffffffffu, mx, 4));
            float mnew = fmaxf(m_i[i], mx);
            float sum = 0.f;
#pragma unroll
            for (int c = 0; c < 8; c++) {
                s[i][c] = __expf(s[i][c] - mnew);
                sum += s[i][c];
            }
            sum += __shfl_xor_sync(0xffffffffu, sum, 1);
            sum += __shfl_xor_sync(0xffffffffu, sum, 2);
            sum += __shfl_xor_sync(0xffffffffu, sum, 4);
            float corr = __expf(m_i[i] - mnew);
            l_i[i] = l_i[i] * corr + sum;
            m_i[i] = mnew;
#pragma unroll
            for (int c = 0; c < 8; c++) O[i][c] *= corr;
        }

        // P -> smem (reuse KtP), then O += P @ V
        __syncthreads();
#pragma unroll
        for (int i = 0; i < 4; i++)
#pragma unroll
            for (int c = 0; c < 8; c++)
                KtP[SW(ty * 4 + i, tx * 8 + c)] = s[i][c];
        __syncthreads();

#pragma unroll 4
        for (int kk = 0; kk < 64; kk++) {
            float pf[4], vf[8];
#pragma unroll
            for (int i = 0; i < 4; i++) pf[i] = KtP[SW(ty * 4 + i, kk)];
#pragma unroll
            for (int c = 0; c < 8; c++) vf[c] = Vs[SW(kk, tx * 8 + c)];
#pragma unroll
            for (int i = 0; i < 4; i++)
#pragma unroll
                for (int c = 0; c < 8; c++)
                    O[i][c] = fmaf(pf[i], vf[c], O[i][c]);
        }
    }

    // epilogue: normalize and scatter to [b, t, h*64+d] layout for output proj
    const int b = bh >> 4, h = bh & 15;
#pragma unroll
    for (int i = 0; i < 4; i++) {
        float inv = 1.f / l_i[i];
        int tq = q0 + ty * 4 + i;
        float* dst = g_att + ((size_t)b * TQN + tq) * D_MODEL + h * DK + tx * 8;
#pragma unroll
        for (int c = 0; c < 8; c++) dst[c] = O[i][c] * inv;
    }
}

// ---------------------------------------------------------------------------
// Output projection: out = g_att @ Wo^T + bo
// ---------------------------------------------------------------------------
__global__ __launch_bounds__(256) void outproj_kernel(const float* __restrict__ Wo,
                                                      const float* __restrict__ bo,
                                                      float* __restrict__ out)
{
    float acc[8][8];
    gemm128(g_att, Wo, acc);

    const int tx = threadIdx.x & 15, ty = threadIdx.x >> 4;
    const int m0 = blockIdx.y << 7, n0 = blockIdx.x << 7;
#pragma unroll
    for (int i = 0; i < 8; i++) {
        int m = m0 + ty * 8 + i;
#pragma unroll
        for (int j = 0; j < 8; j++) {
            int n = n0 + tx * 8 + j;
            out[(size_t)m * D_MODEL + n] = acc[i][j] + bo[n];
        }
    }
}

// ---------------------------------------------------------------------------
// Entry point. Inputs (metadata order):
// 0 query, 1 key, 2 value, 3 past_K, 4 past_V, 5 mask (unused: pure causal),
// 6 Wq, 7 bq, 8 Wk, 9 bk, 10 Wv, 11 bv, 12 Wo, 13 bo
// Output: concat(out [2,2048,1024], K [2,16,4096,64], V [2,16,4096,64]) fp32
// ---------------------------------------------------------------------------
extern "C" void kernel_launch(void* const* d_in, const int* in_sizes, int n_in,
                              void* d_out, int out_size)
{
    (void)in_sizes; (void)n_in; (void)out_size;

    const float* query = (const float*)d_in[0];
    const float* key_  = (const float*)d_in[1];
    const float* value = (const float*)d_in[2];
    const float* pastK = (const float*)d_in[3];
    const float* pastV = (const float*)d_in[4];
    const float* Wq = (const float*)d_in[6];
    const float* bq = (const float*)d_in[7];
    const float* Wk = (const float*)d_in[8];
    const float* bk = (const float*)d_in[9];
    const float* Wv = (const float*)d_in[10];
    const float* bv = (const float*)d_in[11];
    const float* Wo = (const float*)d_in[12];
    const float* bo = (const float*)d_in[13];

    float* out  = (float*)d_out;                             // [2,2048,1024]
    float* kout = out  + (size_t)BB * TQN * D_MODEL;         // [2,16,4096,64]
    float* vout = kout + (size_t)BB * NH * TKV * DK;         // [2,16,4096,64]

    // 1) QKV projections (K/V new tokens written straight into the cache)
    qkv_kernel<<<dim3(8, 32, 3), 256>>>(query, key_, value,
                                        Wq, bq, Wk, bk, Wv, bv, kout, vout);
    // 2) past KV -> cache head
    copy_past_kernel<<<8192, 256>>>((const float4*)pastK, (const float4*)pastV,
                                    (float4*)kout, (float4*)vout);
    // 3) causal flash attention
    flash_kernel<<<dim3(32, 32), 128>>>(kout, vout);
    // 4) output projection
    outproj_kernel<<<dim3(8, 32), 256>>>(Wo, bo, out);
}

// round 4
// speedup vs baseline: 4.9345x; 4.9345x over previous
#include <cuda_runtime.h>
#include <cstdint>

#define D_MODEL 1024
#define NH      16
#define DK      64
#define BB      2
#define TQN     2048
#define TPAST   2048
#define TKV     4096

// Scratch (device globals: no allocation allowed in kernel_launch)
__device__ float g_Q[(size_t)BB * NH * TQN * DK];       // [bh][t][dk]
__device__ float g_att[(size_t)BB * TQN * D_MODEL];     // [b][t][d]

// ---------------------------------------------------------------------------
// tf32 helpers
// ---------------------------------------------------------------------------
__device__ __forceinline__ unsigned f2tf(float x) {
    unsigned u;
    asm("cvt.rna.tf32.f32 %0, %1;" : "=r"(u) : "f"(x));
    return u;
}

// D(16x8,f32) += A(16x8,tf32,row) * B(8x8,tf32,col)
__device__ __forceinline__ void mma8(float d[4], const unsigned a[4],
                                     unsigned b0, unsigned b1) {
    asm volatile(
        "mma.sync.aligned.m16n8k8.row.col.f32.tf32.tf32.f32 "
        "{%0,%1,%2,%3},{%4,%5,%6,%7},{%8,%9},{%0,%1,%2,%3};"
        : "+f"(d[0]), "+f"(d[1]), "+f"(d[2]), "+f"(d[3])
        : "r"(a[0]), "r"(a[1]), "r"(a[2]), "r"(a[3]), "r"(b0), "r"(b1));
}

// ---------------------------------------------------------------------------
// Tensor-core GEMM core: 128x128 tile of C = A[M,1024] @ W[1024,1024]^T
// A row-major [M,1024], W row-major [N,1024] (K-contig -> NT gemm).
// 256 threads = 8 warps (4 m-groups x 2 n-groups); warp: 32(M) x 64(N).
// K-tile 32, fragments from smem (stride 36 words -> conflict-free).
// ---------------------------------------------------------------------------
__device__ __forceinline__ void gemm_tc(const float* __restrict__ A,
                                        const float* __restrict__ W,
                                        float Cacc[2][8][4])
{
    __shared__ __align__(16) unsigned As[128 * 36];
    __shared__ __align__(16) unsigned Bs[128 * 36];

    const int tid = threadIdx.x;
    const int lane = tid & 31;
    const int w = tid >> 5, wm = w & 3, wn = w >> 2;
    const int l4 = lane >> 2, lq = lane & 3;
    const int m0 = blockIdx.y << 7, n0 = blockIdx.x << 7;

#pragma unroll
    for (int mt = 0; mt < 2; mt++)
#pragma unroll
        for (int nt = 0; nt < 8; nt++)
#pragma unroll
            for (int r = 0; r < 4; r++) Cacc[mt][nt][r] = 0.f;

    for (int k0 = 0; k0 < 1024; k0 += 32) {
        __syncthreads();
        // load 128x32 of A and W, convert to tf32, store to smem
        int f = tid;
#pragma unroll
        for (int i = 0; i < 4; i++, f += 256) {
            int r = f >> 3, c4 = (f & 7) << 2;
            float4 a4 = *(const float4*)(A + (size_t)(m0 + r) * 1024 + k0 + c4);
            uint4 ua; ua.x = f2tf(a4.x); ua.y = f2tf(a4.y);
                      ua.z = f2tf(a4.z); ua.w = f2tf(a4.w);
            *(uint4*)&As[r * 36 + c4] = ua;
            float4 b4 = *(const float4*)(W + (size_t)(n0 + r) * 1024 + k0 + c4);
            uint4 ub; ub.x = f2tf(b4.x); ub.y = f2tf(b4.y);
                      ub.z = f2tf(b4.z); ub.w = f2tf(b4.w);
            *(uint4*)&Bs[r * 36 + c4] = ub;
        }
        __syncthreads();

#pragma unroll
        for (int k8 = 0; k8 < 4; k8++) {
            unsigned a[2][4];
#pragma unroll
            for (int mt = 0; mt < 2; mt++) {
                int row = wm * 32 + mt * 16 + l4;
                a[mt][0] = As[row * 36 + k8 * 8 + lq];
                a[mt][1] = As[(row + 8) * 36 + k8 * 8 + lq];
                a[mt][2] = As[row * 36 + k8 * 8 + 4 + lq];
                a[mt][3] = As[(row + 8) * 36 + k8 * 8 + 4 + lq];
            }
#pragma unroll
            for (int nt = 0; nt < 8; nt++) {
                int nrow = wn * 64 + nt * 8 + l4;
                unsigned b0 = Bs[nrow * 36 + k8 * 8 + lq];
                unsigned b1 = Bs[nrow * 36 + k8 * 8 + 4 + lq];
                mma8(Cacc[0][nt], a[0], b0, b1);
                mma8(Cacc[1][nt], a[1], b0, b1);
            }
        }
    }
}

// ---------------------------------------------------------------------------
// QKV projection: z=0 -> Q scratch [bh][t][dk]; z=1/2 -> K/V into cache
// ---------------------------------------------------------------------------
__global__ __launch_bounds__(256, 2) void qkv_kernel(
    const float* __restrict__ q_in, const float* __restrict__ k_in,
    const float* __restrict__ v_in,
    const float* __restrict__ Wq, const float* __restrict__ bq,
    const float* __restrict__ Wk, const float* __restrict__ bk,
    const float* __restrict__ Wv, const float* __restrict__ bv,
    float* __restrict__ k_out, float* __restrict__ v_out)
{
    const int z = blockIdx.z;
    const float* A    = (z == 0) ? q_in : (z == 1) ? k_in : v_in;
    const float* W    = (z == 0) ? Wq   : (z == 1) ? Wk   : Wv;
    const float* bias = (z == 0) ? bq   : (z == 1) ? bk   : bv;

    float Cacc[2][8][4];
    gemm_tc(A, W, Cacc);

    const int tid = threadIdx.x, lane = tid & 31;
    const int w = tid >> 5, wm = w & 3, wn = w >> 2;
    const int l4 = lane >> 2, lq = lane & 3;
    const int m0 = blockIdx.y << 7, n0 = blockIdx.x << 7;

#pragma unroll
    for (int mt = 0; mt < 2; mt++) {
        int mrow = m0 + wm * 32 + mt * 16 + l4;
#pragma unroll
        for (int nt = 0; nt < 8; nt++) {
            int col = n0 + wn * 64 + nt * 8 + 2 * lq;
            float2 bb = *(const float2*)&bias[col];
            float2 v0 = make_float2(Cacc[mt][nt][0] + bb.x, Cacc[mt][nt][1] + bb.y);
            float2 v1 = make_float2(Cacc[mt][nt][2] + bb.x, Cacc[mt][nt][3] + bb.y);
            int h = col >> 6, dk = col & 63;
#pragma unroll
            for (int rr = 0; rr < 2; rr++) {
                int m = mrow + rr * 8;
                int b = m >> 11, tt = m & 2047;
                float2 val = rr ? v1 : v0;
                if (z == 0) {
                    *(float2*)&g_Q[(((size_t)(b * NH + h)) * TQN + tt) * DK + dk] = val;
                } else {
                    float* dst = (z == 1) ? k_out : v_out;
                    *(float2*)&dst[(((size_t)(b * NH + h)) * TKV + TPAST + tt) * DK + dk] = val;
                }
            }
        }
    }
}

// ---------------------------------------------------------------------------
// Copy past_K / past_V into the first TPAST slots of the KV caches.
// ---------------------------------------------------------------------------
__global__ __launch_bounds__(256) void copy_past_kernel(
    const float4* __restrict__ pk, const float4* __restrict__ pv,
    float4* __restrict__ ko, float4* __restrict__ vo)
{
    const int PER_BH_SRC = TPAST * DK / 4;   // 32768
    const int PER_BH_DST = TKV   * DK / 4;   // 65536
    const int TOT = BB * NH * PER_BH_SRC;    // 1048576
    int idx = blockIdx.x * blockDim.x + threadIdx.x;
    int which = idx >= TOT;
    int r = idx - (which ? TOT : 0);
    int bhi = r / PER_BH_SRC;
    int off = r - bhi * PER_BH_SRC;
    const float4* src = which ? pv : pk;
    float4*       dst = which ? vo : ko;
    dst[(size_t)bhi * PER_BH_DST + off] = src[r];
}

// ---------------------------------------------------------------------------
// Flash attention, tensor-core tf32. Block = (b,h) x 128-query tile.
// 256 threads = 8 warps, each warp owns 16 query rows. KV tile = 64.
// Q resident in A-fragments; P built from S C-fragments via lane shuffles.
// ---------------------------------------------------------------------------
__global__ __launch_bounds__(256, 2) void flash_kernel(const float* __restrict__ kc,
                                                       const float* __restrict__ vc)
{
    __shared__ __align__(16) unsigned Ks[64 * 68];
    __shared__ __align__(16) unsigned Vs[64 * 72];

    const int tid = threadIdx.x;
    const int w = tid >> 5, lane = tid & 31;
    const int l4 = lane >> 2, lq = lane & 3;
    const int qi = (int)gridDim.x - 1 - (int)blockIdx.x;  // big tiles first
    const int q0 = qi << 7;
    const int bh = blockIdx.y;

    const float* Qg = g_Q + (size_t)bh * TQN * DK + (size_t)q0 * DK;
    const float* Kg = kc + (size_t)bh * TKV * DK;
    const float* Vg = vc + (size_t)bh * TKV * DK;

    // Q fragments (rows w*16 .. +15), pre-scaled by 1/sqrt(64)=1/8
    unsigned Qa[8][4];
    {
        const float* qr = Qg + (w * 16 + l4) * DK + lq;
#pragma unroll
        for (int kt = 0; kt < 8; kt++) {
            Qa[kt][0] = f2tf(qr[kt * 8] * 0.125f);
            Qa[kt][1] = f2tf(qr[8 * DK + kt * 8] * 0.125f);
            Qa[kt][2] = f2tf(qr[kt * 8 + 4] * 0.125f);
            Qa[kt][3] = f2tf(qr[8 * DK + kt * 8 + 4] * 0.125f);
        }
    }

    float O[8][4];
#pragma unroll
    for (int nd = 0; nd < 8; nd++)
#pragma unroll
        for (int r = 0; r < 4; r++) O[nd][r] = 0.f;
    float m_lo = -1e30f, m_hi = -1e30f, l_lo = 0.f, l_hi = 0.f;

    const int n_tiles = (TPAST + q0 + 128) >> 6;   // last 2 tiles partial

    for (int t = 0; t < n_tiles; t++) {
        const int j0 = t << 6;
        __syncthreads();
        // load K/V 64x64 tiles, tf32-converted
        {
            int f = tid;
#pragma unroll
            for (int i = 0; i < 4; i++, f += 256) {
                int r = f >> 4, c4 = (f & 15) << 2;
                float4 k4 = *(const float4*)(Kg + (size_t)(j0 + r) * DK + c4);
                uint4 uk; uk.x = f2tf(k4.x); uk.y = f2tf(k4.y);
                          uk.z = f2tf(k4.z); uk.w = f2tf(k4.w);
                *(uint4*)&Ks[r * 68 + c4] = uk;
                float4 v4 = *(const float4*)(Vg + (size_t)(j0 + r) * DK + c4);
                uint4 uv; uv.x = f2tf(v4.x); uv.y = f2tf(v4.y);
                          uv.z = f2tf(v4.z); uv.w = f2tf(v4.w);
                *(uint4*)&Vs[r * 72 + c4] = uv;
            }
        }
        __syncthreads();

        // S = Q @ K^T  (per-warp 16x64, 8 independent accumulators)
        float S[8][4];
#pragma unroll
        for (int nt = 0; nt < 8; nt++)
#pragma unroll
            for (int r = 0; r < 4; r++) S[nt][r] = 0.f;

#pragma unroll
        for (int kt = 0; kt < 8; kt++) {
#pragma unroll
            for (int nt = 0; nt < 8; nt++) {
                int base = (nt * 8 + l4) * 68 + kt * 8 + lq;
                mma8(S[nt], Qa[kt], Ks[base], Ks[base + 4]);
            }
        }

        // causal mask (only last two tiles can be partial)
        if (t >= n_tiles - 2) {
            const int lim_lo = TPAST + q0 + w * 16 + l4 - j0;
            const int lim_hi = lim_lo + 8;
#pragma unroll
            for (int nt = 0; nt < 8; nt++) {
                int c0 = nt * 8 + 2 * lq, c1 = c0 + 1;
                if (c0 > lim_lo) S[nt][0] = -1e30f;
                if (c1 > lim_lo) S[nt][1] = -1e30f;
                if (c0 > lim_hi) S[nt][2] = -1e30f;
                if (c1 > lim_hi) S[nt][3] = -1e30f;
            }
        }

        // online softmax (two rows per thread; row spread over 4 lanes)
        float tlo = -1e30f, thi = -1e30f;
#pragma unroll
        for (int nt = 0; nt < 8; nt++) {
            tlo = fmaxf(tlo, fmaxf(S[nt][0], S[nt][1]));
            thi = fmaxf(thi, fmaxf(S[nt][2], S[nt][3]));
        }
        tlo = fmaxf(tlo, __shfl_xor_sync(0xffffffffu, tlo, 1));
        tlo = fmaxf(tlo, __shfl_xor_sync(0xffffffffu, tlo, 2));
        thi = fmaxf(thi, __shfl_xor_sync(0xffffffffu, thi, 1));
        thi = fmaxf(thi, __shfl_xor_sync(0xffffffffu, thi, 2));
        float mnl = fmaxf(m_lo, tlo), mnh = fmaxf(m_hi, thi);
        float corr_lo = __expf(m_lo - mnl), corr_hi = __expf(m_hi - mnh);
        m_lo = mnl; m_hi = mnh;
        float sl = 0.f, sh = 0.f;
#pragma unroll
        for (int nt = 0; nt < 8; nt++) {
            S[nt][0] = __expf(S[nt][0] - m_lo); sl += S[nt][0];
            S[nt][1] = __expf(S[nt][1] - m_lo); sl += S[nt][1];
            S[nt][2] = __expf(S[nt][2] - m_hi); sh += S[nt][2];
            S[nt][3] = __expf(S[nt][3] - m_hi); sh += S[nt][3];
        }
        l_lo = l_lo * corr_lo + sl;
        l_hi = l_hi * corr_hi + sh;
#pragma unroll
        for (int nd = 0; nd < 8; nd++) {
            O[nd][0] *= corr_lo; O[nd][1] *= corr_lo;
            O[nd][2] *= corr_hi; O[nd][3] *= corr_hi;
        }

        // O += P @ V ; P A-fragments built from S C-fragments via shuffles
        const int src0 = (lane & 28) | (lq >> 1);
        const int src1 = src0 + 2;
        const bool odd = lq & 1;
#pragma unroll
        for (int kt = 0; kt < 8; kt++) {
            float e00 = __shfl_sync(0xffffffffu, S[kt][0], src0);
            float e01 = __shfl_sync(0xffffffffu, S[kt][1], src0);
            float e02 = __shfl_sync(0xffffffffu, S[kt][0], src1);
            float e03 = __shfl_sync(0xffffffffu, S[kt][1], src1);
            float f00 = __shfl_sync(0xffffffffu, S[kt][2], src0);
            float f01 = __shfl_sync(0xffffffffu, S[kt][3], src0);
            float f02 = __shfl_sync(0xffffffffu, S[kt][2], src1);
            float f03 = __shfl_sync(0xffffffffu, S[kt][3], src1);
            unsigned Pa[4];
            Pa[0] = f2tf(odd ? e01 : e00);
            Pa[1] = f2tf(odd ? f01 : f00);
            Pa[2] = f2tf(odd ? e03 : e02);
            Pa[3] = f2tf(odd ? f03 : f02);
#pragma unroll
            for (int nd = 0; nd < 8; nd++) {
                unsigned b0 = Vs[(kt * 8 + lq) * 72 + nd * 8 + l4];
                unsigned b1 = Vs[(kt * 8 + 4 + lq) * 72 + nd * 8 + l4];
                mma8(O[nd], Pa, b0, b1);
            }
        }
    }

    // epilogue: reduce l over the quad, normalize, scatter to [b][t][h*64+d]
    l_lo += __shfl_xor_sync(0xffffffffu, l_lo, 1);
    l_lo += __shfl_xor_sync(0xffffffffu, l_lo, 2);
    l_hi += __shfl_xor_sync(0xffffffffu, l_hi, 1);
    l_hi += __shfl_xor_sync(0xffffffffu, l_hi, 2);
    float inv_lo = 1.f / l_lo, inv_hi = 1.f / l_hi;

    const int b = bh >> 4, h = bh & 15;
    const int row_lo = q0 + w * 16 + l4;
    float* base_lo = g_att + ((size_t)b * TQN + row_lo) * D_MODEL + h * DK;
    float* base_hi = base_lo + (size_t)8 * D_MODEL;
#pragma unroll
    for (int nd = 0; nd < 8; nd++) {
        *(float2*)(base_lo + nd * 8 + 2 * lq) =
            make_float2(O[nd][0] * inv_lo, O[nd][1] * inv_lo);
        *(float2*)(base_hi + nd * 8 + 2 * lq) =
            make_float2(O[nd][2] * inv_hi, O[nd][3] * inv_hi);
    }
}

// ---------------------------------------------------------------------------
// Output projection: out = g_att @ Wo^T + bo
// ---------------------------------------------------------------------------
__global__ __launch_bounds__(256, 2) void outproj_kernel(const float* __restrict__ Wo,
                                                         const float* __restrict__ bo,
                                                         float* __restrict__ out)
{
    float Cacc[2][8][4];
    gemm_tc(g_att, Wo, Cacc);

    const int tid = threadIdx.x, lane = tid & 31;
    const int w = tid >> 5, wm = w & 3, wn = w >> 2;
    const int l4 = lane >> 2, lq = lane & 3;
    const int m0 = blockIdx.y << 7, n0 = blockIdx.x << 7;

#pragma unroll
    for (int mt = 0; mt < 2; mt++) {
        int mrow = m0 + wm * 32 + mt * 16 + l4;
#pragma unroll
        for (int nt = 0; nt < 8; nt++) {
            int col = n0 + wn * 64 + nt * 8 + 2 * lq;
            float2 bb = *(const float2*)&bo[col];
            *(float2*)&out[(size_t)mrow * D_MODEL + col] =
                make_float2(Cacc[mt][nt][0] + bb.x, Cacc[mt][nt][1] + bb.y);
            *(float2*)&out[(size_t)(mrow + 8) * D_MODEL + col] =
                make_float2(Cacc[mt][nt][2] + bb.x, Cacc[mt][nt][3] + bb.y);
        }
    }
}

// ---------------------------------------------------------------------------
// Entry point. Inputs: 0 query, 1 key, 2 value, 3 past_K, 4 past_V,
// 5 mask (unused: analytic causal), 6..13 Wq,bq,Wk,bk,Wv,bv,Wo,bo
// Output: concat(out [2,2048,1024], K [2,16,4096,64], V [2,16,4096,64]) fp32
// ---------------------------------------------------------------------------
extern "C" void kernel_launch(void* const* d_in, const int* in_sizes, int n_in,
                              void* d_out, int out_size)
{
    (void)in_sizes; (void)n_in; (void)out_size;

    const float* query = (const float*)d_in[0];
    const float* key_  = (const float*)d_in[1];
    const float* value = (const float*)d_in[2];
    const float* pastK = (const float*)d_in[3];
    const float* pastV = (const float*)d_in[4];
    const float* Wq = (const float*)d_in[6];
    const float* bq = (const float*)d_in[7];
    const float* Wk = (const float*)d_in[8];
    const float* bk = (const float*)d_in[9];
    const float* Wv = (const float*)d_in[10];
    const float* bv = (const float*)d_in[11];
    const float* Wo = (const float*)d_in[12];
    const float* bo = (const float*)d_in[13];

    float* out  = (float*)d_out;                             // [2,2048,1024]
    float* kout = out  + (size_t)BB * TQN * D_MODEL;         // [2,16,4096,64]
    float* vout = kout + (size_t)BB * NH * TKV * DK;         // [2,16,4096,64]

    qkv_kernel<<<dim3(8, 32, 3), 256>>>(query, key_, value,
                                        Wq, bq, Wk, bk, Wv, bv, kout, vout);
    copy_past_kernel<<<8192, 256>>>((const float4*)pastK, (const float4*)pastV,
                                    (float4*)kout, (float4*)vout);
    flash_kernel<<<dim3(16, 32), 256>>>(kout, vout);
    outproj_kernel<<<dim3(8, 32), 256>>>(Wo, bo, out);
}